// round 14
// baseline (speedup 1.0000x reference)
#include <cuda_runtime.h>
#include <cstdint>

// CTC loss, probability-domain DP, per-lane block-float exponents.
// R14: forward/backward midpoint split. Per batch element, TWO warps run in
// parallel: fwd computes alpha over t=0..255, bwd computes beta over
// t=511..256 (mirrored recurrence); exact combine
//   P = sum_s alpha_255[s] * (beta_256[s] + beta_256[s+1] + allow[s+2]*beta_256[s+2]).
// Doubles warp parallelism (1024 warps) and halves serial depth, letting all
// 148 SMs run ~7 warps each (R13 showed 8 warps/SM ~ 2.1x per-SM throughput).
// 4 warps/CTA (2 batch elems), 96KB smem, grid=256 -> 2 CTAs/SM, one wave.
// B=512, T=512, C=128, L=64, S=129, blank=127.

#define CTC_B 512
#define CTC_T 512
#define CTC_C 128
#define CTC_L 64
#define CH    8                   // rows per chunk = rescale period
#define RCH   6                   // ring slots per warp (24 KB)
#define LA    (RCH - 1)           // lookahead chunks (5)
#define NCHH  (CTC_T / 2 / CH)    // 32 chunks per half
#define WPB   4                   // warps per CTA (2 fwd/bwd pairs)
#define RING_F (RCH * CH * CTC_C) // 6144 floats per warp ring
#define SMEM_BYTES (WPB * RING_F * 4)   // 98304 B

__global__ void __launch_bounds__(WPB * 32, 2) ctc_kernel(
    const int* __restrict__ y_true,
    const float* __restrict__ y_pred,
    float* __restrict__ out)
{
    extern __shared__ float smem[];

    const float EPS = 1e-7f;
    const float LN2 = 0.69314718055994530942f;
    const unsigned FULL = 0xffffffffu;
    const int w    = threadIdx.x >> 5;
    const int lane = threadIdx.x & 31;
    const int pair = w >> 1;                 // batch pair within CTA
    const int dir  = w & 1;                  // 0 = forward, 1 = backward
    const int b    = blockIdx.x * 2 + pair;

    float* ring = smem + w * RING_F;         // private 24 KB ring

    const int* lrow = y_true + b * CTC_L;
    const int lab1 = lrow[2 * lane];
    const int lab3 = lrow[2 * lane + 1];
    const int prev1 = (lane > 0) ? lrow[2 * lane - 1] : -1;
    const bool allow1 = (lane > 0) && (lab1 != prev1);
    const bool allow3 = (lab3 != lab1);
    const int labn2 = (lane < 31) ? lrow[2 * lane + 2] : 0;
    const bool allow1n = (lane < 31) && (labn2 != lab3);  // skip 4l+3 -> 4l+5

    const float* base = y_pred + (size_t)b * CTC_T * CTC_C;
    const unsigned smb = (unsigned)__cvta_generic_to_shared(ring);
    const unsigned lane4 = 4u * lane;

    // Issue one chunk of 8 rows. Forward: rows c*8+r. Backward: rows 511-(c*8+r).
    auto issue_chunk = [&](int c, int slot) {
        const unsigned sbase = (unsigned)slot * (CH * CTC_C);
#pragma unroll
        for (int r = 0; r < CH; ++r) {
            const int row = dir ? (CTC_T - 1 - (c * CH + r)) : (c * CH + r);
            const float* src = base + (size_t)row * CTC_C + lane4;
            const unsigned dst = smb + (sbase + (unsigned)r * CTC_C + lane4) * 4u;
            asm volatile("cp.async.cg.shared.global [%0], [%1], 16;"
                         :: "r"(dst), "l"(src));
        }
        asm volatile("cp.async.commit_group;");
    };

#pragma unroll
    for (int c = 0; c < LA; ++c) issue_chunk(c, c);

    // state registers (alpha for fwd, beta for bwd)
    float v0, v1 = 0.0f, v2 = 0.0f, v3 = 0.0f, v4;
    v0 = (!dir && lane == 0) ? 1.0f : 0.0f;   // fwd virtual pre-init
    v4 = (dir && lane == 31) ? 1.0f : 0.0f;   // bwd virtual pre-init (s=128)
    int   E = 0;
    float f = 1.0f;                            // neighbor re-basing factor
    if (!dir && lane == 0) f = 0.0f;           // fwd lane0 has no lane -1

    int rslot = 0, wslot = LA;

    for (int c = 0; c < NCHH; ++c) {
        if (c + LA < NCHH) issue_chunk(c + LA, wslot);
        else asm volatile("cp.async.commit_group;");
        asm volatile("cp.async.wait_group %0;" :: "n"(LA));
        __syncwarp();

        const int cb = rslot * (CH * CTC_C);
        float pb[CH], p1[CH], p3[CH];
#pragma unroll
        for (int j = 0; j < CH; ++j) {
            const int rb = cb + j * CTC_C;
            pb[j] = ring[rb + (CTC_C - 1)] + EPS;
            p1[j] = ring[rb + lab1] + EPS;
            p3[j] = ring[rb + lab3] + EPS;
        }

        if (!dir) {
            // ---- forward DP (proven R6) ----
#pragma unroll
            for (int j = 0; j < CH; ++j) {
                const float am1 = __shfl_up_sync(FULL, v3, 1) * f;
                const float n0 = (v0 + am1) * pb[j];
                const float n1 = (v1 + v0 + (allow1 ? am1 : 0.0f)) * p1[j];
                const float n2 = (v2 + v1) * pb[j];
                const float n3 = (v3 + v2 + (allow3 ? v1 : 0.0f)) * p3[j];
                const float n4 = (v4 + v3) * pb[j];
                v0 = n0; v1 = n1; v2 = n2; v3 = n3; v4 = n4;
            }
            // rescale + upward zero-adoption (mass flows lane l-1 -> l)
            float lm = fmaxf(fmaxf(v0, v1), fmaxf(v2, v3));
            lm = fmaxf(lm, v4);
            int e = (int)(__float_as_uint(lm) >> 23) - 127;
            const bool zero = (lm == 0.0f);
            if (zero) e = 0;
            const float sc = __uint_as_float((unsigned)(127 - e) << 23);
            v0 *= sc; v1 *= sc; v2 *= sc; v3 *= sc; v4 *= sc;
            E += e;
            const int Ep = __shfl_up_sync(FULL, E, 1);
            if (zero && lane > 0) E = Ep;
            const int Ep2 = __shfl_up_sync(FULL, E, 1);
            int d = Ep2 - E;
            d = max(-126, min(126, d));
            f = __uint_as_float((unsigned)(127 + d) << 23);
            if (lane == 0) f = 0.0f;
        } else {
            // ---- backward DP (mirror; mass flows lane l+1 -> l) ----
#pragma unroll
            for (int j = 0; j < CH; ++j) {
                float bn0 = __shfl_down_sync(FULL, v0, 1) * f;  // state 4l+4
                float bn1 = __shfl_down_sync(FULL, v1, 1) * f;  // state 4l+5
                if (lane == 31) { bn0 = v4; bn1 = 0.0f; }       // s127 -> s128
                const float n0 = pb[j] * (v0 + v1);
                const float n1 = p1[j] * (v1 + v2 + (allow3 ? v3 : 0.0f));
                const float n2 = pb[j] * (v2 + v3);
                const float n3 = p3[j] * (v3 + bn0 + (allow1n ? bn1 : 0.0f));
                const float n4 = pb[j] * v4;                    // s128 self-loop
                v0 = n0; v1 = n1; v2 = n2; v3 = n3; v4 = n4;
            }
            float lm = fmaxf(fmaxf(v0, v1), fmaxf(v2, v3));
            lm = fmaxf(lm, v4);
            int e = (int)(__float_as_uint(lm) >> 23) - 127;
            const bool zero = (lm == 0.0f);
            if (zero) e = 0;
            const float sc = __uint_as_float((unsigned)(127 - e) << 23);
            v0 *= sc; v1 *= sc; v2 *= sc; v3 *= sc; v4 *= sc;
            E += e;
            const int Ep = __shfl_down_sync(FULL, E, 1);
            if (zero && lane < 31) E = Ep;
            const int Ep2 = __shfl_down_sync(FULL, E, 1);
            int d = Ep2 - E;                 // lane31: shfl returns own -> d=0, f=1
            d = max(-126, min(126, d));
            f = __uint_as_float((unsigned)(127 + d) << 23);
        }

        rslot = (rslot + 1 == RCH) ? 0 : rslot + 1;
        wslot = (wslot + 1 == RCH) ? 0 : wslot + 1;
    }

    // publish final state + exponent into own ring (all real transfers drained)
    ring[0 * 32 + lane] = v0;
    ring[1 * 32 + lane] = v1;
    ring[2 * 32 + lane] = v2;
    ring[3 * 32 + lane] = v3;
    ring[4 * 32 + lane] = v4;
    ring[5 * 32 + lane] = __int_as_float(E);
    __syncthreads();

    if (!dir) {
        // ---- combine: P = sum_s alpha[s] * bhat[s] ----
        const float* pr = smem + (w + 1) * RING_F;   // partner (bwd) ring
        const float B0 = pr[0 * 32 + lane];
        const float B1 = pr[1 * 32 + lane];
        const float B2 = pr[2 * 32 + lane];
        const float B3 = pr[3 * 32 + lane];
        const float B4 = pr[4 * 32 + lane];
        const int   Eb = __float_as_int(pr[5 * 32 + lane]);
        float B0n = 0.0f, B1n = 0.0f;
        int   Ebn = Eb;
        if (lane < 31) {
            B0n = pr[0 * 32 + lane + 1];
            B1n = pr[1 * 32 + lane + 1];
            Ebn = __float_as_int(pr[5 * 32 + lane + 1]);
        } else {
            B0n = B4;            // state 128, already in own frame
            B1n = 0.0f;
        }
        int dn = Ebn - Eb;
        dn = max(-126, min(126, dn));
        float fn = __uint_as_float((unsigned)(127 + dn) << 23);
        if (lane == 31) fn = 1.0f;

        float contrib =
            v0 * (B0 + B1) +
            v1 * (B1 + B2 + (allow3 ? B3 : 0.0f)) +
            v2 * (B2 + B3) +
            v3 * (B3 + fn * (B0n + (allow1n ? B1n : 0.0f)));
        if (lane == 31) contrib += v4 * B4;

        int e = E + Eb;
        int m = e;
#pragma unroll
        for (int o = 16; o; o >>= 1) m = max(m, __shfl_xor_sync(FULL, m, o));
        const int dd = e - m;                              // <= 0
        const float sc = (dd < -126) ? 0.0f
                       : __uint_as_float((unsigned)(127 + dd) << 23);
        float tot = contrib * sc;
#pragma unroll
        for (int o = 16; o; o >>= 1) tot += __shfl_xor_sync(FULL, tot, o);

        if (lane == 0) out[b] = -(__logf(tot) + (float)m * LN2);
    }
}

extern "C" void kernel_launch(void* const* d_in, const int* in_sizes, int n_in,
                              void* d_out, int out_size) {
    const int*   y_true = (const int*)d_in[0];
    const float* y_pred = (const float*)d_in[1];
    float*       outp   = (float*)d_out;
    (void)in_sizes; (void)n_in; (void)out_size;

    cudaFuncSetAttribute(ctc_kernel,
                         cudaFuncAttributeMaxDynamicSharedMemorySize, SMEM_BYTES);
    ctc_kernel<<<CTC_B / 2, WPB * 32, SMEM_BYTES>>>(y_true, y_pred, outp);
}

// round 15
// speedup vs baseline: 1.5638x; 1.5638x over previous
#include <cuda_runtime.h>
#include <cstdint>

// CTC loss, probability-domain forward DP, per-lane block-float exponents.
// R15 = R6 (best: 26.7us, DRAM-ceiling-bound at ~5.4 TB/s) with two bit-exact
// serial-overhead cuts: (1) allow-terms as 0/1-mask FFMA (saves 2 issue
// slots/step), (2) one wait_group+syncwarp per TWO chunks (16 steps) instead
// of one. Rescale numerics unchanged (proven).
// B=512, T=512, C=128, L=64, S=129, blank=127. One warp per batch element.

#define CTC_B 512
#define CTC_T 512
#define CTC_C 128
#define CTC_L 64
#define CH    8                 // rows per chunk = rescale period
#define RCH   8                 // ring slots (32 KB smem)
#define WA    6                 // write-ahead distance (chunks)
#define NCH   (CTC_T / CH)      // 64 chunks

__global__ __launch_bounds__(32) void ctc_kernel(
    const int* __restrict__ y_true,
    const float* __restrict__ y_pred,
    float* __restrict__ out)
{
    __shared__ float ring[RCH * CH * CTC_C];   // 32 KB

    const float EPS = 1e-7f;
    const unsigned FULL = 0xffffffffu;
    const int b    = blockIdx.x;
    const int lane = threadIdx.x;

    // labels for odd states s=4l+1 (label 2l) and s=4l+3 (label 2l+1)
    const int* lrow = y_true + b * CTC_L;
    const int lab1 = lrow[2 * lane];
    const int lab3 = lrow[2 * lane + 1];
    const int prev1 = (lane > 0) ? lrow[2 * lane - 1] : -1;
    const float m1 = ((lane > 0) && (lab1 != prev1)) ? 1.0f : 0.0f; // skip into 4l+1
    const float m3 = (lab3 != lab1) ? 1.0f : 0.0f;                  // skip into 4l+3

    const float* base = y_pred + (size_t)b * CTC_T * CTC_C;
    const unsigned smb = (unsigned)__cvta_generic_to_shared(ring);
    const unsigned lane4 = 4u * lane;

    // Issue one chunk into slot c&7: 8 rows, 1 cp.async.cg 16B per lane per
    // row, 1 commit.
    auto issue_chunk = [&](int c) {
        const unsigned sbase = (unsigned)(c & (RCH - 1)) * (CH * CTC_C);
#pragma unroll
        for (int r = 0; r < CH; ++r) {
            const float* src = base + (size_t)(c * CH + r) * CTC_C + lane4;
            const unsigned dst = smb + (sbase + (unsigned)r * CTC_C + lane4) * 4u;
            asm volatile("cp.async.cg.shared.global [%0], [%1], 16;"
                         :: "r"(dst), "l"(src));
        }
        asm volatile("cp.async.commit_group;");
    };

    // Prologue: fill WA chunks (slots 0..5).
#pragma unroll
    for (int c = 0; c < WA; ++c) issue_chunk(c);

    // virtual pre-init: a0=1 on lane 0 makes step t=0 yield the reference init
    float a0 = (lane == 0) ? 1.0f : 0.0f;
    float a1 = 0.0f, a2 = 0.0f, a3 = 0.0f, a4 = 0.0f;
    int   E  = 0;                            // alpha = a * 2^E (per lane)
    float f  = (lane == 0) ? 0.0f : 1.0f;    // neighbor re-basing factor

    // Process one chunk: 24 LDS gathers + 8 DP steps + rescale (R6-exact).
    auto do_chunk = [&](int c) {
        const int cb = (c & (RCH - 1)) * (CH * CTC_C);
        float pb[CH], p1[CH], p3[CH];
#pragma unroll
        for (int j = 0; j < CH; ++j) {
            const int rb = cb + j * CTC_C;
            pb[j] = ring[rb + (CTC_C - 1)] + EPS;   // blank: broadcast LDS
            p1[j] = ring[rb + lab1] + EPS;
            p3[j] = ring[rb + lab3] + EPS;
        }
#pragma unroll
        for (int j = 0; j < CH; ++j) {
            const float am1 = __shfl_up_sync(FULL, a3, 1) * f;   // lane0: f=0

            const float n0 = (a0 + am1) * pb[j];                 // s=4l (blank)
            const float n1 = fmaf(am1, m1, a1 + a0) * p1[j];     // s=4l+1
            const float n2 = (a2 + a1) * pb[j];                  // s=4l+2 (blank)
            const float n3 = fmaf(a1, m3, a3 + a2) * p3[j];      // s=4l+3
            const float n4 = (a4 + a3) * pb[j];                  // s=128 (lane31)
            a0 = n0; a1 = n1; a2 = n2; a3 = n3; a4 = n4;
        }
        // ---- per-lane power-of-2 rescale (exact R6 logic) ----
        float lm = fmaxf(fmaxf(a0, a1), fmaxf(a2, a3));
        lm = fmaxf(lm, a4);
        int e = (int)(__float_as_uint(lm) >> 23) - 127;
        const bool zero = (lm == 0.0f);
        if (zero) e = 0;
        const float sc = __uint_as_float((unsigned)(127 - e) << 23); // 2^-e
        a0 *= sc; a1 *= sc; a2 *= sc; a3 *= sc; a4 *= sc;
        E += e;
        // all-zero lanes (ahead of the DP wavefront) adopt neighbor's frame
        const int Ep = __shfl_up_sync(FULL, E, 1);
        if (zero && lane > 0) E = Ep;
        // neighbor re-basing factor for the next chunk
        const int Ep2 = __shfl_up_sync(FULL, E, 1);
        int d = Ep2 - E;
        d = max(-126, min(126, d));
        f = __uint_as_float((unsigned)(127 + d) << 23);  // 2^d
        if (lane == 0) f = 0.0f;
    };

    for (int c = 0; c < NCH; c += 2) {
        // Issue chunks c+6, c+7 into slots (c-2)&7, (c-1)&7 — both were read
        // in iteration c-2/c-1 (register-consumed before these issues).
        if (c + WA < NCH) issue_chunk(c + WA);
        else asm volatile("cp.async.commit_group;");
        if (c + WA + 1 < NCH) issue_chunk(c + WA + 1);
        else asm volatile("cp.async.commit_group;");

        // committed = c+8 groups; pending <= 6 -> chunks 0..c+1 complete
        asm volatile("cp.async.wait_group %0;" :: "n"(WA));
        __syncwarp();

        do_chunk(c);
        do_chunk(c + 1);
    }

    if (lane == 31) {
        // P_total = alpha_{T-1}[S-1] + alpha_{T-1}[S-2] = (a4 + a3) * 2^E
        const float p = a4 + a3;
        out[b] = -(__logf(p) + (float)E * 0.69314718055994530942f);
    }
}

extern "C" void kernel_launch(void* const* d_in, const int* in_sizes, int n_in,
                              void* d_out, int out_size) {
    const int*   y_true = (const int*)d_in[0];
    const float* y_pred = (const float*)d_in[1];
    float*       outp   = (float*)d_out;
    (void)in_sizes; (void)n_in; (void)out_size;

    ctc_kernel<<<CTC_B, 32>>>(y_true, y_pred, outp);
}